// round 1
// baseline (speedup 1.0000x reference)
#include <cuda_runtime.h>
#include <cstdint>
#include <cstdio>

// ---------------- problem constants ----------------
#define BB      2
#define LL      2048
#define DM      768          // D_MODEL
#define DIN     384          // D_IN
#define DINNER  768          // D_INNER
#define DTR     24           // DT_RANK
#define DST     16           // D_STATE
#define XZW     1536         // 2*D_INNER
#define XDW     56           // DTR + 2*DST
#define NROWS   (BB*LL)      // 4096
#define EPSV    1e-5f

// ---------------- scratch (static device globals; no runtime alloc) ----------
__device__ float g_xn [NROWS*DM];        // layernormed input
__device__ float g_xp [NROWS*DM];        // input projection (fwd|bwd)
__device__ float g_xz [2][NROWS*XZW];    // per-dir in-proj output (x|z)
__device__ float g_xc [2][NROWS*DINNER]; // conv+silu output
__device__ float g_xd [2][NROWS*XDW];    // x @ xp_w  (dt_low | B | C)
__device__ float g_dt [2][NROWS*DINNER]; // softplus(dt)
__device__ float g_y  [2][NROWS*DINNER]; // scan output (gated)
__device__ float g_cat[NROWS*DM];        // concat(out_fwd, out_bwd)
__device__ float g_tmp[NROWS*DM];        // op projection

// ---------------- layernorm (optionally fused residual add) ------------------
__global__ void ln_kernel(const float* __restrict__ a,
                          const float* __restrict__ add,   // nullable
                          const float* __restrict__ w,
                          const float* __restrict__ b,
                          float* __restrict__ out)
{
    int row = blockIdx.x;
    const float* pa = a + (size_t)row * DM;
    const float* pd = add ? add + (size_t)row * DM : nullptr;

    float v[3];
    float s = 0.f, sq = 0.f;
#pragma unroll
    for (int i = 0; i < 3; i++) {
        int idx = threadIdx.x + i * 256;
        float t = pa[idx];
        if (pd) t += pd[idx];
        v[i] = t;
        s += t; sq += t * t;
    }
#pragma unroll
    for (int o = 16; o; o >>= 1) {
        s  += __shfl_xor_sync(0xffffffffu, s,  o);
        sq += __shfl_xor_sync(0xffffffffu, sq, o);
    }
    __shared__ float ss[8], ssq[8];
    int wid = threadIdx.x >> 5, ln = threadIdx.x & 31;
    if (ln == 0) { ss[wid] = s; ssq[wid] = sq; }
    __syncthreads();
    if (threadIdx.x == 0) {
        float S = 0.f, Q = 0.f;
#pragma unroll
        for (int i = 0; i < 8; i++) { S += ss[i]; Q += ssq[i]; }
        ss[0] = S; ssq[0] = Q;
    }
    __syncthreads();
    float mean = ss[0] * (1.f / DM);
    float var  = ssq[0] * (1.f / DM) - mean * mean;
    float rs   = rsqrtf(var + EPSV);

    float* po = out + (size_t)row * DM;
#pragma unroll
    for (int i = 0; i < 3; i++) {
        int idx = threadIdx.x + i * 256;
        po[idx] = (v[i] - mean) * rs * w[idx] + b[idx];
    }
}

// ---------------- generic fp32 tiled GEMM: C = act(rowmap(A[:,acol:]) @ W + bias)
// A row-major with leading dim lda; W is K x N row-major; optional L-flip on
// source rows (aflip) and destination rows (cflip) within each batch of LL rows.
#define ACT_NONE 0
#define ACT_SOFTPLUS 1

__global__ void gemm_kernel(const float* __restrict__ A, int lda, int acol, int aflip,
                            const float* __restrict__ W,
                            const float* __restrict__ bias,
                            float* __restrict__ C, int ldc, int ccol, int cflip,
                            int M, int N, int K, int act)
{
    const int BM = 64, BN = 64, BK = 16;
    __shared__ __align__(16) float As[BK][BM + 4];
    __shared__ __align__(16) float Bs[BK][BN];

    int bm = blockIdx.y * BM;
    int bn = blockIdx.x * BN;
    int tid = threadIdx.x;
    int tr = tid >> 4;            // 0..15
    int tc = tid & 15;            // 0..15

    float acc[4][4];
#pragma unroll
    for (int i = 0; i < 4; i++)
#pragma unroll
        for (int j = 0; j < 4; j++) acc[i][j] = 0.f;

    for (int k0 = 0; k0 < K; k0 += BK) {
        // load A tile (BM x BK)
        for (int i = tid; i < BM * BK; i += 256) {
            int r = i >> 4, c = i & 15;
            int gr = bm + r, gc = k0 + c;
            float v = 0.f;
            if (gr < M && gc < K) {
                int srow = gr;
                if (aflip) { int b = gr / LL, l = gr % LL; srow = b * LL + (LL - 1 - l); }
                v = A[(size_t)srow * lda + acol + gc];
            }
            As[c][r] = v;
        }
        // load W tile (BK x BN)
        for (int i = tid; i < BK * BN; i += 256) {
            int r = i >> 6, c = i & 63;
            int gr = k0 + r, gc = bn + c;
            Bs[r][c] = (gr < K && gc < N) ? W[(size_t)gr * N + gc] : 0.f;
        }
        __syncthreads();
#pragma unroll
        for (int k = 0; k < BK; k++) {
            float4 a4 = *reinterpret_cast<const float4*>(&As[k][tr * 4]);
            float4 b4 = *reinterpret_cast<const float4*>(&Bs[k][tc * 4]);
            float a[4] = {a4.x, a4.y, a4.z, a4.w};
            float b[4] = {b4.x, b4.y, b4.z, b4.w};
#pragma unroll
            for (int i = 0; i < 4; i++)
#pragma unroll
                for (int j = 0; j < 4; j++)
                    acc[i][j] = fmaf(a[i], b[j], acc[i][j]);
        }
        __syncthreads();
    }

#pragma unroll
    for (int i = 0; i < 4; i++) {
        int gr = bm + tr * 4 + i;
        if (gr >= M) continue;
        int drow = gr;
        if (cflip) { int b = gr / LL, l = gr % LL; drow = b * LL + (LL - 1 - l); }
#pragma unroll
        for (int j = 0; j < 4; j++) {
            int gc = bn + tc * 4 + j;
            if (gc >= N) continue;
            float v = acc[i][j] + (bias ? bias[gc] : 0.f);
            if (act == ACT_SOFTPLUS) v = (v > 20.f) ? v : log1pf(__expf(v));
            C[(size_t)drow * ldc + ccol + gc] = v;
        }
    }
}

// ---------------- causal depthwise conv (K=4) + SiLU -------------------------
__global__ void conv_silu_kernel(const float* __restrict__ xz,   // [NROWS][XZW], x in cols [0,DINNER)
                                 const float* __restrict__ cw,   // [DINNER][4]
                                 const float* __restrict__ cb,   // [DINNER]
                                 float* __restrict__ out)        // [NROWS][DINNER]
{
    int idx = blockIdx.x * blockDim.x + threadIdx.x;
    if (idx >= NROWS * DINNER) return;
    int d = idx % DINNER;
    int row = idx / DINNER;
    int b = row / LL, l = row % LL;

    float acc = cb[d];
#pragma unroll
    for (int k = 0; k < 4; k++) {
        int ls = l - 3 + k;
        if (ls >= 0)
            acc = fmaf(cw[d * 4 + k], xz[((size_t)b * LL + ls) * XZW + d], acc);
    }
    out[idx] = acc / (1.f + __expf(-acc));   // silu
}

// ---------------- selective scan ---------------------------------------------
// One warp handles 2 channels; lane%16 = state index n. Sequential over L.
// Epilogue fused: y = (sum_n h*C + x*D) * silu(z)
__global__ void scan_kernel(const float* __restrict__ dt,    // [NROWS][DINNER]
                            const float* __restrict__ xc,    // [NROWS][DINNER]
                            const float* __restrict__ xd,    // [NROWS][XDW]  (B at 24, C at 40)
                            const float* __restrict__ xz,    // [NROWS][XZW]  (z at DINNER)
                            const float* __restrict__ A_log, // [DINNER][DST]
                            const float* __restrict__ Dp,    // [DINNER]
                            float* __restrict__ y)           // [NROWS][DINNER]
{
    int lane = threadIdx.x & 31;
    int warp = threadIdx.x >> 5;
    int n = lane & 15;
    int ch = blockIdx.x * 16 + warp * 2 + (lane >> 4);
    int b = blockIdx.y;
    size_t rowbase = (size_t)b * LL;

    float Ac = -__expf(A_log[ch * DST + n]);
    float Dv = Dp[ch];
    float h = 0.f;

    for (int t = 0; t < LL; t++) {
        size_t r = rowbase + t;
        float dtv = __ldg(dt + r * DINNER + ch);
        float xv  = __ldg(xc + r * DINNER + ch);
        float Bv  = __ldg(xd + r * XDW + DTR + n);
        float Cv  = __ldg(xd + r * XDW + DTR + DST + n);

        float a = __expf(dtv * Ac);
        h = fmaf(a, h, dtv * xv * Bv);
        float yp = h * Cv;
#pragma unroll
        for (int o = 8; o; o >>= 1)
            yp += __shfl_xor_sync(0xffffffffu, yp, o, 16);
        if (n == 0) {
            float zv = __ldg(xz + r * XZW + DINNER + ch);
            float sz = zv / (1.f + __expf(-zv));
            y[r * DINNER + ch] = (yp + xv * Dv) * sz;
        }
    }
}

// ---------------- host side --------------------------------------------------
static void launch_gemm(const float* A, int lda, int acol, int aflip,
                        const float* W, const float* bias,
                        float* C, int ldc, int ccol, int cflip,
                        int M, int N, int K, int act)
{
    dim3 grid((N + 63) / 64, (M + 63) / 64);
    gemm_kernel<<<grid, 256>>>(A, lda, acol, aflip, W, bias, C, ldc, ccol, cflip, M, N, K, act);
}

extern "C" void kernel_launch(void* const* d_in, const int* in_sizes, int n_in,
                              void* d_out, int out_size)
{
    const float* x         = (const float*)d_in[0];
    const float* in_norm_w = (const float*)d_in[1];
    const float* in_norm_b = (const float*)d_in[2];
    const float* ip_w      = (const float*)d_in[3];
    const float* ip_b      = (const float*)d_in[4];
    // per-direction params: f at base 5, b at base 16
    const float* dir_in_w [2] = {(const float*)d_in[5],  (const float*)d_in[16]};
    const float* dir_in_b [2] = {(const float*)d_in[6],  (const float*)d_in[17]};
    const float* dir_cw   [2] = {(const float*)d_in[7],  (const float*)d_in[18]};
    const float* dir_cb   [2] = {(const float*)d_in[8],  (const float*)d_in[19]};
    const float* dir_xp_w [2] = {(const float*)d_in[9],  (const float*)d_in[20]};
    const float* dir_dt_w [2] = {(const float*)d_in[10], (const float*)d_in[21]};
    const float* dir_dt_b [2] = {(const float*)d_in[11], (const float*)d_in[22]};
    const float* dir_Alog [2] = {(const float*)d_in[12], (const float*)d_in[23]};
    const float* dir_D    [2] = {(const float*)d_in[13], (const float*)d_in[24]};
    const float* dir_ow   [2] = {(const float*)d_in[14], (const float*)d_in[25]};
    const float* dir_ob   [2] = {(const float*)d_in[15], (const float*)d_in[26]};
    const float* op_w      = (const float*)d_in[27];
    const float* op_b      = (const float*)d_in[28];
    const float* norm_w    = (const float*)d_in[29];
    const float* norm_b    = (const float*)d_in[30];
    float* out = (float*)d_out;

    // resolve scratch symbols
    void* p;
    cudaGetSymbolAddress(&p, g_xn);  float* xn  = (float*)p;
    cudaGetSymbolAddress(&p, g_xp);  float* xp  = (float*)p;
    cudaGetSymbolAddress(&p, g_xz);  float* xzb = (float*)p;
    cudaGetSymbolAddress(&p, g_xc);  float* xcb = (float*)p;
    cudaGetSymbolAddress(&p, g_xd);  float* xdb = (float*)p;
    cudaGetSymbolAddress(&p, g_dt);  float* dtb = (float*)p;
    cudaGetSymbolAddress(&p, g_y);   float* yb  = (float*)p;
    cudaGetSymbolAddress(&p, g_cat); float* cat = (float*)p;
    cudaGetSymbolAddress(&p, g_tmp); float* tmp = (float*)p;

    // 1) input layernorm
    ln_kernel<<<NROWS, 256>>>(x, nullptr, in_norm_w, in_norm_b, xn);

    // 2) input projection: xp = xn @ ip_w + ip_b   (4096x768 @ 768x768)
    launch_gemm(xn, DM, 0, 0, ip_w, ip_b, xp, DM, 0, 0, NROWS, DM, DM, ACT_NONE);

    for (int dir = 0; dir < 2; dir++) {
        float* xz = xzb + (size_t)dir * NROWS * XZW;
        float* xc = xcb + (size_t)dir * NROWS * DINNER;
        float* xd = xdb + (size_t)dir * NROWS * XDW;
        float* dt = dtb + (size_t)dir * NROWS * DINNER;
        float* y  = yb  + (size_t)dir * NROWS * DINNER;

        // 3) xz = u @ in_w + in_b ; u = xp[:, dir*384 : dir*384+384] (bwd: L-flipped)
        launch_gemm(xp, DM, dir * DIN, dir, dir_in_w[dir], dir_in_b[dir],
                    xz, XZW, 0, 0, NROWS, XZW, DIN, ACT_NONE);

        // 4) causal conv1d + silu on x-half
        conv_silu_kernel<<<(NROWS * DINNER) / 256, 256>>>(xz, dir_cw[dir], dir_cb[dir], xc);

        // 5) xd = xc @ xp_w  (no bias)   4096x768 @ 768x56
        launch_gemm(xc, DINNER, 0, 0, dir_xp_w[dir], nullptr,
                    xd, XDW, 0, 0, NROWS, XDW, DINNER, ACT_NONE);

        // 6) dt = softplus(xd[:, :24] @ dt_w + dt_b)   4096x24 @ 24x768
        launch_gemm(xd, XDW, 0, 0, dir_dt_w[dir], dir_dt_b[dir],
                    dt, DINNER, 0, 0, NROWS, DINNER, DTR, ACT_SOFTPLUS);

        // 7) selective scan (fused: +x*D, *silu(z))
        scan_kernel<<<dim3(DINNER / 16, BB), 256>>>(dt, xc, xd, xz,
                                                    dir_Alog[dir], dir_D[dir], y);

        // 8) out projection into concat buffer (bwd: un-flip rows on store)
        launch_gemm(y, DINNER, 0, 0, dir_ow[dir], dir_ob[dir],
                    cat, DM, dir * DIN, dir, NROWS, DIN, DINNER, ACT_NONE);
    }

    // 9) final projection
    launch_gemm(cat, DM, 0, 0, op_w, op_b, tmp, DM, 0, 0, NROWS, DM, DM, ACT_NONE);

    // 10) residual add + layernorm -> out
    ln_kernel<<<NROWS, 256>>>(tmp, x, norm_w, norm_b, out);

    (void)in_sizes; (void)n_in; (void)out_size;
}

// round 2
// speedup vs baseline: 2.4681x; 2.4681x over previous
#include <cuda_runtime.h>
#include <cstdint>

// ---------------- problem constants ----------------
#define BB      2
#define LL      2048
#define DM      768          // D_MODEL
#define DIN     384          // D_IN
#define DINNER  768          // D_INNER
#define DTR     24           // DT_RANK
#define DST     16           // D_STATE
#define XZW     1536         // 2*D_INNER
#define NROWS   (BB*LL)      // 4096
#define WCN     800          // 768 (dt) + 32 (B,C)
#define EPSV    1e-5f

// ---------------- scratch (static device globals) ----------------------------
__device__ float g_xn [NROWS*DM];        // layernormed input
__device__ float g_xp [NROWS*DM];        // input projection output
__device__ float g_xz [2][NROWS*XZW];    // per-dir in-proj (x|z)
__device__ float g_xc [2][NROWS*DINNER]; // conv+silu output
__device__ float g_bc [2][NROWS*32];     // B (16) | C (16)
__device__ float g_dt [2][NROWS*DINNER]; // softplus(dt)
__device__ float g_y  [2][NROWS*DINNER]; // scan output (gated)
__device__ float g_cat[NROWS*DM];        // concat(out_fwd, out_bwd)
__device__ float g_tmp[NROWS*DM];        // op projection
__device__ float g_wc [2][DINNER*WCN];   // combined dt/BC weight

// ---------------- helpers ----------------------------------------------------
__device__ __forceinline__ uint32_t f2tf(float f) {
    uint32_t r;
    asm("cvt.rna.tf32.f32 %0, %1;" : "=r"(r) : "f"(f));
    return r;
}

// ---------------- layernorm (optionally fused residual add) ------------------
__global__ void ln_kernel(const float* __restrict__ a,
                          const float* __restrict__ add,
                          const float* __restrict__ w,
                          const float* __restrict__ b,
                          float* __restrict__ out)
{
    int row = blockIdx.x;
    const float* pa = a + (size_t)row * DM;
    const float* pd = add ? add + (size_t)row * DM : nullptr;

    float v[3];
    float s = 0.f, sq = 0.f;
#pragma unroll
    for (int i = 0; i < 3; i++) {
        int idx = threadIdx.x + i * 256;
        float t = pa[idx];
        if (pd) t += pd[idx];
        v[i] = t;
        s += t; sq += t * t;
    }
#pragma unroll
    for (int o = 16; o; o >>= 1) {
        s  += __shfl_xor_sync(0xffffffffu, s,  o);
        sq += __shfl_xor_sync(0xffffffffu, sq, o);
    }
    __shared__ float ss[8], ssq[8];
    int wid = threadIdx.x >> 5, ln = threadIdx.x & 31;
    if (ln == 0) { ss[wid] = s; ssq[wid] = sq; }
    __syncthreads();
    if (threadIdx.x == 0) {
        float S = 0.f, Q = 0.f;
#pragma unroll
        for (int i = 0; i < 8; i++) { S += ss[i]; Q += ssq[i]; }
        ss[0] = S; ssq[0] = Q;
    }
    __syncthreads();
    float mean = ss[0] * (1.f / DM);
    float var  = ssq[0] * (1.f / DM) - mean * mean;
    float rs   = rsqrtf(var + EPSV);

    float* po = out + (size_t)row * DM;
#pragma unroll
    for (int i = 0; i < 3; i++) {
        int idx = threadIdx.x + i * 256;
        po[idx] = (v[i] - mean) * rs * w[idx] + b[idx];
    }
}

// ---------------- combined dt/BC weight precompute ----------------------------
// wc[k][n<768] = sum_r xp_w[k][r] * dt_w[r][n] ; wc[k][768+j] = xp_w[k][24+j]
__global__ void wc_kernel(const float* __restrict__ xp_w,  // [768][56]
                          const float* __restrict__ dt_w,  // [24][768]
                          float* __restrict__ wc)          // [768][800]
{
    int i = blockIdx.x * 256 + threadIdx.x;
    if (i >= DINNER * WCN) return;
    int k = i / WCN, n = i % WCN;
    if (n < DINNER) {
        float s = 0.f;
#pragma unroll
        for (int r = 0; r < DTR; r++)
            s = fmaf(xp_w[k * 56 + r], dt_w[r * DINNER + n], s);
        wc[i] = s;
    } else {
        wc[i] = xp_w[k * 56 + DTR + (n - DINNER)];
    }
}

// ---------------- tf32 tensor-core GEMM ---------------------------------------
// C = act(A[:, acol:acol+K] @ W + bias)
// mode 0: out0[row*ldc + ccol + col] = v (+bias)
// mode 1 (dtbc): col<768 -> out0[row*768+col] = softplus(v + bias[col])
//                col>=768 -> out1[row*32 + col-768] = v
__global__ __launch_bounds__(256, 2)
void tf32_gemm(const float* __restrict__ A, int lda, int acol,
               const float* __restrict__ W, int N, int K,
               const float* __restrict__ bias,
               float* __restrict__ out0, int ldc, int ccol,
               float* __restrict__ out1, int mode)
{
    const int BM = 128, BN = 64, BK = 16;
    __shared__ float As[BK][BM + 8];
    __shared__ float Bs[BK][BN + 8];

    int bm = blockIdx.y * BM;
    int bn = blockIdx.x * BN;
    int tid = threadIdx.x, lane = tid & 31, warp = tid >> 5;
    int wm = warp >> 1, wn = warp & 1;       // 4x2 warp grid
    int gid = lane >> 2, tid4 = lane & 3;

    float acc[2][4][4];
#pragma unroll
    for (int a = 0; a < 2; a++)
#pragma unroll
        for (int b = 0; b < 4; b++)
#pragma unroll
            for (int c = 0; c < 4; c++) acc[a][b][c] = 0.f;

    for (int k0 = 0; k0 < K; k0 += BK) {
        // A tile: 128x16, 512 float4 loads across 256 threads (2 each)
#pragma unroll
        for (int j = 0; j < 2; j++) {
            int i = tid + j * 256;
            int row = i >> 2, kq = (i & 3) * 4;
            float4 v = *reinterpret_cast<const float4*>(
                A + (size_t)(bm + row) * lda + acol + k0 + kq);
            As[kq + 0][row] = v.x;
            As[kq + 1][row] = v.y;
            As[kq + 2][row] = v.z;
            As[kq + 3][row] = v.w;
        }
        // B tile: 16x64, 1 float4 per thread
        {
            int row = tid >> 4, nq = (tid & 15) * 4;
            int gn = bn + nq;
            float4 v;
            if (gn + 3 < N) {
                v = *reinterpret_cast<const float4*>(W + (size_t)(k0 + row) * N + gn);
            } else {
                const float* p = W + (size_t)(k0 + row) * N;
                v.x = (gn + 0 < N) ? p[gn + 0] : 0.f;
                v.y = (gn + 1 < N) ? p[gn + 1] : 0.f;
                v.z = (gn + 2 < N) ? p[gn + 2] : 0.f;
                v.w = (gn + 3 < N) ? p[gn + 3] : 0.f;
            }
            *reinterpret_cast<float4*>(&Bs[row][nq]) = v;
        }
        __syncthreads();

#pragma unroll
        for (int ks = 0; ks < 2; ks++) {
            int kb = ks * 8;
            uint32_t af[2][4], bf[4][2];
#pragma unroll
            for (int mt = 0; mt < 2; mt++) {
                int m0 = wm * 32 + mt * 16 + gid;
                af[mt][0] = f2tf(As[kb + tid4][m0]);
                af[mt][1] = f2tf(As[kb + tid4][m0 + 8]);
                af[mt][2] = f2tf(As[kb + tid4 + 4][m0]);
                af[mt][3] = f2tf(As[kb + tid4 + 4][m0 + 8]);
            }
#pragma unroll
            for (int nt = 0; nt < 4; nt++) {
                int n0 = wn * 32 + nt * 8 + gid;
                bf[nt][0] = f2tf(Bs[kb + tid4][n0]);
                bf[nt][1] = f2tf(Bs[kb + tid4 + 4][n0]);
            }
#pragma unroll
            for (int mt = 0; mt < 2; mt++)
#pragma unroll
                for (int nt = 0; nt < 4; nt++) {
                    asm volatile(
                        "mma.sync.aligned.m16n8k8.row.col.f32.tf32.tf32.f32 "
                        "{%0,%1,%2,%3}, {%4,%5,%6,%7}, {%8,%9}, {%0,%1,%2,%3};\n"
                        : "+f"(acc[mt][nt][0]), "+f"(acc[mt][nt][1]),
                          "+f"(acc[mt][nt][2]), "+f"(acc[mt][nt][3])
                        : "r"(af[mt][0]), "r"(af[mt][1]), "r"(af[mt][2]), "r"(af[mt][3]),
                          "r"(bf[nt][0]), "r"(bf[nt][1]));
                }
        }
        __syncthreads();
    }

    // epilogue
#pragma unroll
    for (int mt = 0; mt < 2; mt++) {
#pragma unroll
        for (int nt = 0; nt < 4; nt++) {
#pragma unroll
            for (int c = 0; c < 4; c++) {
                int row = bm + wm * 32 + mt * 16 + gid + ((c >= 2) ? 8 : 0);
                int col = bn + wn * 32 + nt * 8 + tid4 * 2 + (c & 1);
                if (col >= N) continue;
                float v = acc[mt][nt][c];
                if (mode == 0) {
                    if (bias) v += bias[col];
                    out0[(size_t)row * ldc + ccol + col] = v;
                } else {
                    if (col < DINNER) {
                        v += bias[col];
                        v = (v > 20.f) ? v : log1pf(__expf(v));
                        out0[(size_t)row * DINNER + col] = v;
                    } else {
                        out1[(size_t)row * 32 + (col - DINNER)] = v;
                    }
                }
            }
        }
    }
}

// ---------------- causal/anti-causal depthwise conv (K=4) + SiLU --------------
// both directions in one launch: blockIdx.y = dir
__global__ void conv_silu2(const float* __restrict__ xz0, const float* __restrict__ xz1,
                           const float* __restrict__ cw0, const float* __restrict__ cb0,
                           const float* __restrict__ cw1, const float* __restrict__ cb1,
                           float* __restrict__ out0, float* __restrict__ out1)
{
    int dir = blockIdx.y;
    const float* xz = dir ? xz1 : xz0;
    const float* cw = dir ? cw1 : cw0;
    const float* cb = dir ? cb1 : cb0;
    float* out = dir ? out1 : out0;

    int idx = blockIdx.x * blockDim.x + threadIdx.x;
    if (idx >= NROWS * DINNER) return;
    int d = idx % DINNER;
    int row = idx / DINNER;
    int b = row / LL, l = row % LL;

    float acc = cb[d];
    if (dir == 0) {
#pragma unroll
        for (int k = 0; k < 4; k++) {
            int ls = l - 3 + k;
            if (ls >= 0)
                acc = fmaf(cw[d * 4 + k], xz[((size_t)b * LL + ls) * XZW + d], acc);
        }
    } else {
        // flip(causal_conv(flip(u)))[l] = sum_k w[k] * u[l + 3 - k]
#pragma unroll
        for (int k = 0; k < 4; k++) {
            int ls = l + 3 - k;
            if (ls < LL)
                acc = fmaf(cw[d * 4 + k], xz[((size_t)b * LL + ls) * XZW + d], acc);
        }
    }
    out[idx] = acc / (1.f + __expf(-acc));   // silu
}

// ---------------- selective scan (both dirs, prefetched) ----------------------
// grid (DINNER/16, BB, 2); warp handles 2 channels; lane%16 = state index
__global__ void scan2(const float* __restrict__ dt0, const float* __restrict__ dt1,
                      const float* __restrict__ xc0, const float* __restrict__ xc1,
                      const float* __restrict__ bc0, const float* __restrict__ bc1,
                      const float* __restrict__ xz0, const float* __restrict__ xz1,
                      const float* __restrict__ A0,  const float* __restrict__ A1,
                      const float* __restrict__ D0,  const float* __restrict__ D1,
                      float* __restrict__ y0,        float* __restrict__ y1)
{
    int dir = blockIdx.z;
    const float* dt = dir ? dt1 : dt0;
    const float* xc = dir ? xc1 : xc0;
    const float* bc = dir ? bc1 : bc0;
    const float* xz = dir ? xz1 : xz0;
    const float* Al = dir ? A1 : A0;
    const float* Dp = dir ? D1 : D0;
    float* y = dir ? y1 : y0;

    int lane = threadIdx.x & 31;
    int warp = threadIdx.x >> 5;
    int n = lane & 15;
    int ch = blockIdx.x * 16 + warp * 2 + (lane >> 4);
    size_t rowbase = (size_t)blockIdx.y * LL;

    float Ac = -__expf(Al[ch * DST + n]);
    float Dv = Dp[ch];
    float h = 0.f;

    int t = dir ? (LL - 1) : 0;
    int step = dir ? -1 : 1;

    size_t r = rowbase + t;
    float dtv = __ldg(dt + r * DINNER + ch);
    float xv  = __ldg(xc + r * DINNER + ch);
    float Bv  = __ldg(bc + r * 32 + n);
    float Cv  = __ldg(bc + r * 32 + 16 + n);
    float zv  = (n == 0) ? __ldg(xz + r * XZW + DINNER + ch) : 0.f;

    for (int s = 0; s < LL; s++) {
        float dtv2 = 0.f, xv2 = 0.f, Bv2 = 0.f, Cv2 = 0.f, zv2 = 0.f;
        size_t rn = 0;
        if (s + 1 < LL) {
            rn = rowbase + (t + step);
            dtv2 = __ldg(dt + rn * DINNER + ch);
            xv2  = __ldg(xc + rn * DINNER + ch);
            Bv2  = __ldg(bc + rn * 32 + n);
            Cv2  = __ldg(bc + rn * 32 + 16 + n);
            if (n == 0) zv2 = __ldg(xz + rn * XZW + DINNER + ch);
        }

        float a = __expf(dtv * Ac);
        h = fmaf(a, h, dtv * xv * Bv);
        float yp = h * Cv;
#pragma unroll
        for (int o = 8; o; o >>= 1)
            yp += __shfl_xor_sync(0xffffffffu, yp, o, 16);
        if (n == 0) {
            float sz = zv / (1.f + __expf(-zv));
            y[r * DINNER + ch] = (yp + xv * Dv) * sz;
        }

        dtv = dtv2; xv = xv2; Bv = Bv2; Cv = Cv2; zv = zv2;
        r = rn; t += step;
    }
}

// ---------------- host side ---------------------------------------------------
static void launch_gemm(const float* A, int lda, int acol,
                        const float* W, int N, int K,
                        const float* bias,
                        float* out0, int ldc, int ccol,
                        float* out1, int mode)
{
    dim3 grid((N + 63) / 64, NROWS / 128);
    tf32_gemm<<<grid, 256>>>(A, lda, acol, W, N, K, bias, out0, ldc, ccol, out1, mode);
}

extern "C" void kernel_launch(void* const* d_in, const int* in_sizes, int n_in,
                              void* d_out, int out_size)
{
    const float* x         = (const float*)d_in[0];
    const float* in_norm_w = (const float*)d_in[1];
    const float* in_norm_b = (const float*)d_in[2];
    const float* ip_w      = (const float*)d_in[3];
    const float* ip_b      = (const float*)d_in[4];
    const float* dir_in_w [2] = {(const float*)d_in[5],  (const float*)d_in[16]};
    const float* dir_in_b [2] = {(const float*)d_in[6],  (const float*)d_in[17]};
    const float* dir_cw   [2] = {(const float*)d_in[7],  (const float*)d_in[18]};
    const float* dir_cb   [2] = {(const float*)d_in[8],  (const float*)d_in[19]};
    const float* dir_xp_w [2] = {(const float*)d_in[9],  (const float*)d_in[20]};
    const float* dir_dt_w [2] = {(const float*)d_in[10], (const float*)d_in[21]};
    const float* dir_dt_b [2] = {(const float*)d_in[11], (const float*)d_in[22]};
    const float* dir_Alog [2] = {(const float*)d_in[12], (const float*)d_in[23]};
    const float* dir_D    [2] = {(const float*)d_in[13], (const float*)d_in[24]};
    const float* dir_ow   [2] = {(const float*)d_in[14], (const float*)d_in[25]};
    const float* dir_ob   [2] = {(const float*)d_in[15], (const float*)d_in[26]};
    const float* op_w      = (const float*)d_in[27];
    const float* op_b      = (const float*)d_in[28];
    const float* norm_w    = (const float*)d_in[29];
    const float* norm_b    = (const float*)d_in[30];
    float* out = (float*)d_out;

    void* p;
    cudaGetSymbolAddress(&p, g_xn);  float* xn  = (float*)p;
    cudaGetSymbolAddress(&p, g_xp);  float* xp  = (float*)p;
    cudaGetSymbolAddress(&p, g_xz);  float* xzb = (float*)p;
    cudaGetSymbolAddress(&p, g_xc);  float* xcb = (float*)p;
    cudaGetSymbolAddress(&p, g_bc);  float* bcb = (float*)p;
    cudaGetSymbolAddress(&p, g_dt);  float* dtb = (float*)p;
    cudaGetSymbolAddress(&p, g_y);   float* yb  = (float*)p;
    cudaGetSymbolAddress(&p, g_cat); float* cat = (float*)p;
    cudaGetSymbolAddress(&p, g_tmp); float* tmp = (float*)p;
    cudaGetSymbolAddress(&p, g_wc);  float* wcb = (float*)p;

    float* xz[2] = {xzb, xzb + (size_t)NROWS * XZW};
    float* xc[2] = {xcb, xcb + (size_t)NROWS * DINNER};
    float* bc[2] = {bcb, bcb + (size_t)NROWS * 32};
    float* dt[2] = {dtb, dtb + (size_t)NROWS * DINNER};
    float* yy[2] = {yb,  yb  + (size_t)NROWS * DINNER};
    float* wc[2] = {wcb, wcb + (size_t)DINNER * WCN};

    // 0) combined dt/BC weights (independent of activations)
    int wcg = (DINNER * WCN + 255) / 256;
    wc_kernel<<<wcg, 256>>>(dir_xp_w[0], dir_dt_w[0], wc[0]);
    wc_kernel<<<wcg, 256>>>(dir_xp_w[1], dir_dt_w[1], wc[1]);

    // 1) input layernorm
    ln_kernel<<<NROWS, 256>>>(x, nullptr, in_norm_w, in_norm_b, xn);

    // 2) input projection: xp = xn @ ip_w + ip_b
    launch_gemm(xn, DM, 0, ip_w, DM, DM, ip_b, xp, DM, 0, nullptr, 0);

    // 3) per-dir in-proj: xz = xp[:, dir*384:+384] @ in_w + in_b (natural order)
    for (int d = 0; d < 2; d++)
        launch_gemm(xp, DM, d * DIN, dir_in_w[d], XZW, DIN, dir_in_b[d],
                    xz[d], XZW, 0, nullptr, 0);

    // 4) depthwise conv + silu, both dirs
    conv_silu2<<<dim3((NROWS * DINNER) / 256, 2), 256>>>(
        xz[0], xz[1], dir_cw[0], dir_cb[0], dir_cw[1], dir_cb[1], xc[0], xc[1]);

    // 5) combined dt / B,C GEMM per dir
    for (int d = 0; d < 2; d++)
        launch_gemm(xc[d], DINNER, 0, wc[d], WCN, DINNER, dir_dt_b[d],
                    dt[d], 0, 0, bc[d], 1);

    // 6) selective scan, both dirs
    scan2<<<dim3(DINNER / 16, BB, 2), 256>>>(
        dt[0], dt[1], xc[0], xc[1], bc[0], bc[1], xz[0], xz[1],
        dir_Alog[0], dir_Alog[1], dir_D[0], dir_D[1], yy[0], yy[1]);

    // 7) out projections into concat buffer
    for (int d = 0; d < 2; d++)
        launch_gemm(yy[d], DINNER, 0, dir_ow[d], DIN, DINNER, dir_ob[d],
                    cat, DM, d * DIN, nullptr, 0);

    // 8) final projection
    launch_gemm(cat, DM, 0, op_w, DM, DM, op_b, tmp, DM, 0, nullptr, 0);

    // 9) residual add + layernorm
    ln_kernel<<<NROWS, 256>>>(tmp, x, norm_w, norm_b, out);

    (void)in_sizes; (void)n_in; (void)out_size;
}

// round 3
// speedup vs baseline: 3.5685x; 1.4458x over previous
#include <cuda_runtime.h>
#include <cstdint>

// ---------------- problem constants ----------------
#define BB      2
#define LL      2048
#define DM      768
#define DIN     384
#define DINNER  768
#define DTR     24
#define DST     16
#define XZW     1536
#define NROWS   (BB*LL)
#define WCN     800
#define EPSV    1e-5f

// ---------------- scratch ----------------
__device__ float g_xn [NROWS*DM];
__device__ float g_xp [NROWS*DM];
__device__ float g_xz [2][NROWS*XZW];
__device__ float g_xc [2][NROWS*DINNER];
__device__ float g_bc [2][NROWS*32];
__device__ float g_dt [2][NROWS*DINNER];
__device__ float g_y  [2][NROWS*DINNER];
__device__ float g_cat[NROWS*DM];
__device__ float g_tmp[NROWS*DM];
__device__ float g_wc [2][DINNER*WCN];

// ---------------- cp.async helpers ----------------
__device__ __forceinline__ void cp16(uint32_t dst, const void* src, int srcsize) {
    asm volatile("cp.async.cg.shared.global [%0], [%1], 16, %2;\n"
                 :: "r"(dst), "l"(src), "r"(srcsize));
}
#define CP_COMMIT asm volatile("cp.async.commit_group;\n" ::: "memory")
#define CP_WAIT0  asm volatile("cp.async.wait_group 0;\n" ::: "memory")

// ---------------- layernorm (optional fused residual) ----------------
__global__ void ln_kernel(const float* __restrict__ a,
                          const float* __restrict__ add,
                          const float* __restrict__ w,
                          const float* __restrict__ b,
                          float* __restrict__ out)
{
    int row = blockIdx.x;
    const float* pa = a + (size_t)row * DM;
    const float* pd = add ? add + (size_t)row * DM : nullptr;

    float v[3];
    float s = 0.f, sq = 0.f;
#pragma unroll
    for (int i = 0; i < 3; i++) {
        int idx = threadIdx.x + i * 256;
        float t = pa[idx];
        if (pd) t += pd[idx];
        v[i] = t;
        s += t; sq += t * t;
    }
#pragma unroll
    for (int o = 16; o; o >>= 1) {
        s  += __shfl_xor_sync(0xffffffffu, s,  o);
        sq += __shfl_xor_sync(0xffffffffu, sq, o);
    }
    __shared__ float ss[8], ssq[8];
    int wid = threadIdx.x >> 5, ln = threadIdx.x & 31;
    if (ln == 0) { ss[wid] = s; ssq[wid] = sq; }
    __syncthreads();
    if (threadIdx.x == 0) {
        float S = 0.f, Q = 0.f;
#pragma unroll
        for (int i = 0; i < 8; i++) { S += ss[i]; Q += ssq[i]; }
        ss[0] = S; ssq[0] = Q;
    }
    __syncthreads();
    float mean = ss[0] * (1.f / DM);
    float var  = ssq[0] * (1.f / DM) - mean * mean;
    float rs   = rsqrtf(var + EPSV);

    float* po = out + (size_t)row * DM;
#pragma unroll
    for (int i = 0; i < 3; i++) {
        int idx = threadIdx.x + i * 256;
        po[idx] = (v[i] - mean) * rs * w[idx] + b[idx];
    }
}

// ---------------- combined dt/BC weight precompute ----------------
__global__ void wc_kernel(const float* __restrict__ xp_w,  // [768][56]
                          const float* __restrict__ dt_w,  // [24][768]
                          float* __restrict__ wc)          // [768][800]
{
    int i = blockIdx.x * 256 + threadIdx.x;
    if (i >= DINNER * WCN) return;
    int k = i / WCN, n = i % WCN;
    if (n < DINNER) {
        float s = 0.f;
#pragma unroll
        for (int r = 0; r < DTR; r++)
            s = fmaf(xp_w[k * 56 + r], dt_w[r * DINNER + n], s);
        wc[i] = s;
    } else {
        wc[i] = xp_w[k * 56 + DTR + (n - DINNER)];
    }
}

// ---------------- tf32 tensor-core GEMM, cp.async double-buffered -------------
// blockIdx.z selects direction-parameter set (for paired launches).
// mode 0: out0[row*ldc + ccol + col] = v + bias
// mode 1: col<768 -> out0[row*768+col] = softplus(v+bias); else out1[row*32+col-768]=v
#define BM 128
#define BN 64
#define BKK 16
#define APITCH 20
#define BPITCH 72

__global__ __launch_bounds__(256, 3)
void tf32_gemm(const float* __restrict__ A0, const float* __restrict__ A1,
               int lda, int acol0, int acol1,
               const float* __restrict__ W0, const float* __restrict__ W1,
               int N, int K,
               const float* __restrict__ bias0, const float* __restrict__ bias1,
               float* o00, float* o01, int ldc, int ccol0, int ccol1,
               float* o10, float* o11, int mode)
{
    int z = blockIdx.z;
    const float* A    = z ? A1 : A0;
    const float* W    = z ? W1 : W0;
    const float* bias = z ? bias1 : bias0;
    float* out0 = z ? o01 : o00;
    float* out1 = z ? o11 : o10;
    int acol = z ? acol1 : acol0;
    int ccol = z ? ccol1 : ccol0;

    __shared__ float As[2][BM][APITCH];
    __shared__ float Bs[2][BKK][BPITCH];

    int bm = blockIdx.y * BM;
    int bn = blockIdx.x * BN;
    int tid = threadIdx.x, lane = tid & 31, warp = tid >> 5;
    int wm = warp >> 1, wn = warp & 1;
    int gid = lane >> 2, tid4 = lane & 3;

    // cp.async destination coords (fixed per thread)
    int am0 = (tid * 2) >> 2,     ak0 = ((tid * 2) & 3) * 4;
    int am1 = (tid * 2 + 1) >> 2, ak1 = ((tid * 2 + 1) & 3) * 4;
    int brow = tid >> 4, bnq = (tid & 15) * 4;
    int gn = bn + bnq;
    int bsz = (gn + 3 < N) ? 16 : 0;
    const float* wsrc_base = W + (size_t)brow * N + (bsz ? gn : 0);

    float acc[2][4][4];
#pragma unroll
    for (int a = 0; a < 2; a++)
#pragma unroll
        for (int b = 0; b < 4; b++)
#pragma unroll
            for (int c = 0; c < 4; c++) acc[a][b][c] = 0.f;

    const float* asrc0 = A + (size_t)(bm + am0) * lda + acol + ak0;
    const float* asrc1 = A + (size_t)(bm + am1) * lda + acol + ak1;

    // prologue: load tile 0 into stage 0
    cp16((uint32_t)__cvta_generic_to_shared(&As[0][am0][ak0]), asrc0, 16);
    cp16((uint32_t)__cvta_generic_to_shared(&As[0][am1][ak1]), asrc1, 16);
    cp16((uint32_t)__cvta_generic_to_shared(&Bs[0][brow][bnq]), wsrc_base, bsz);
    CP_COMMIT;

    int niter = K / BKK;
    int cur = 0;
    for (int i = 0; i < niter; i++) {
        CP_WAIT0;
        __syncthreads();
        if (i + 1 < niter) {
            int k0 = (i + 1) * BKK;
            cp16((uint32_t)__cvta_generic_to_shared(&As[cur ^ 1][am0][ak0]), asrc0 + k0, 16);
            cp16((uint32_t)__cvta_generic_to_shared(&As[cur ^ 1][am1][ak1]), asrc1 + k0, 16);
            cp16((uint32_t)__cvta_generic_to_shared(&Bs[cur ^ 1][brow][bnq]),
                 wsrc_base + (size_t)k0 * N, bsz);
            CP_COMMIT;
        }

#pragma unroll
        for (int ks = 0; ks < 2; ks++) {
            int kb = ks * 8;
            uint32_t af[2][4], bf[4][2];
#pragma unroll
            for (int mt = 0; mt < 2; mt++) {
                int m0 = wm * 32 + mt * 16 + gid;
                af[mt][0] = __float_as_uint(As[cur][m0][kb + tid4]);
                af[mt][1] = __float_as_uint(As[cur][m0 + 8][kb + tid4]);
                af[mt][2] = __float_as_uint(As[cur][m0][kb + tid4 + 4]);
                af[mt][3] = __float_as_uint(As[cur][m0 + 8][kb + tid4 + 4]);
            }
#pragma unroll
            for (int nt = 0; nt < 4; nt++) {
                int n0 = wn * 32 + nt * 8 + gid;
                bf[nt][0] = __float_as_uint(Bs[cur][kb + tid4][n0]);
                bf[nt][1] = __float_as_uint(Bs[cur][kb + tid4 + 4][n0]);
            }
#pragma unroll
            for (int mt = 0; mt < 2; mt++)
#pragma unroll
                for (int nt = 0; nt < 4; nt++) {
                    asm volatile(
                        "mma.sync.aligned.m16n8k8.row.col.f32.tf32.tf32.f32 "
                        "{%0,%1,%2,%3}, {%4,%5,%6,%7}, {%8,%9}, {%0,%1,%2,%3};\n"
                        : "+f"(acc[mt][nt][0]), "+f"(acc[mt][nt][1]),
                          "+f"(acc[mt][nt][2]), "+f"(acc[mt][nt][3])
                        : "r"(af[mt][0]), "r"(af[mt][1]), "r"(af[mt][2]), "r"(af[mt][3]),
                          "r"(bf[nt][0]), "r"(bf[nt][1]));
                }
        }
        __syncthreads();
        cur ^= 1;
    }

    // epilogue
#pragma unroll
    for (int mt = 0; mt < 2; mt++) {
#pragma unroll
        for (int nt = 0; nt < 4; nt++) {
#pragma unroll
            for (int c = 0; c < 4; c++) {
                int row = bm + wm * 32 + mt * 16 + gid + ((c >= 2) ? 8 : 0);
                int col = bn + wn * 32 + nt * 8 + tid4 * 2 + (c & 1);
                if (col >= N) continue;
                float v = acc[mt][nt][c];
                if (mode == 0) {
                    if (bias) v += bias[col];
                    out0[(size_t)row * ldc + ccol + col] = v;
                } else {
                    if (col < DINNER) {
                        v += bias[col];
                        v = (v > 20.f) ? v : log1pf(__expf(v));
                        out0[(size_t)row * DINNER + col] = v;
                    } else {
                        out1[(size_t)row * 32 + (col - DINNER)] = v;
                    }
                }
            }
        }
    }
}

// ---------------- causal/anti-causal depthwise conv + SiLU ----------------
__global__ void conv_silu2(const float* __restrict__ xz0, const float* __restrict__ xz1,
                           const float* __restrict__ cw0, const float* __restrict__ cb0,
                           const float* __restrict__ cw1, const float* __restrict__ cb1,
                           float* __restrict__ out0, float* __restrict__ out1)
{
    int dir = blockIdx.y;
    const float* xz = dir ? xz1 : xz0;
    const float* cw = dir ? cw1 : cw0;
    const float* cb = dir ? cb1 : cb0;
    float* out = dir ? out1 : out0;

    int idx = blockIdx.x * blockDim.x + threadIdx.x;
    if (idx >= NROWS * DINNER) return;
    int d = idx % DINNER;
    int row = idx / DINNER;
    int b = row / LL, l = row % LL;

    float acc = cb[d];
    if (dir == 0) {
#pragma unroll
        for (int k = 0; k < 4; k++) {
            int ls = l - 3 + k;
            if (ls >= 0)
                acc = fmaf(cw[d * 4 + k], xz[((size_t)b * LL + ls) * XZW + d], acc);
        }
    } else {
#pragma unroll
        for (int k = 0; k < 4; k++) {
            int ls = l + 3 - k;
            if (ls < LL)
                acc = fmaf(cw[d * 4 + k], xz[((size_t)b * LL + ls) * XZW + d], acc);
        }
    }
    out[idx] = acc / (1.f + __expf(-acc));
}

// ---------------- selective scan (both dirs, distance-2 prefetch) ------------
__global__ void scan2(const float* __restrict__ dt0, const float* __restrict__ dt1,
                      const float* __restrict__ xc0, const float* __restrict__ xc1,
                      const float* __restrict__ bc0, const float* __restrict__ bc1,
                      const float* __restrict__ xz0, const float* __restrict__ xz1,
                      const float* __restrict__ A0,  const float* __restrict__ A1,
                      const float* __restrict__ D0,  const float* __restrict__ D1,
                      float* __restrict__ y0,        float* __restrict__ y1)
{
    int dir = blockIdx.z;
    const float* dt = dir ? dt1 : dt0;
    const float* xc = dir ? xc1 : xc0;
    const float* bc = dir ? bc1 : bc0;
    const float* xz = dir ? xz1 : xz0;
    const float* Al = dir ? A1 : A0;
    const float* Dp = dir ? D1 : D0;
    float* y = dir ? y1 : y0;

    int lane = threadIdx.x & 31;
    int warp = threadIdx.x >> 5;
    int n = lane & 15;
    int ch = blockIdx.x * 16 + warp * 2 + (lane >> 4);
    size_t rowbase = (size_t)blockIdx.y * LL;

    float Ac = -__expf(Al[ch * DST + n]);
    float Dv = Dp[ch];
    float h = 0.f;

    int t0 = dir ? (LL - 1) : 0;
    int step = dir ? -1 : 1;

    float pdt[2], pxv[2], pB[2], pC[2], pz[2];
#pragma unroll
    for (int j = 0; j < 2; j++) {
        size_t r = rowbase + t0 + j * step;
        pdt[j] = __ldg(dt + r * DINNER + ch);
        pxv[j] = __ldg(xc + r * DINNER + ch);
        pB[j]  = __ldg(bc + r * 32 + n);
        pC[j]  = __ldg(bc + r * 32 + 16 + n);
        pz[j]  = (n == 0) ? __ldg(xz + r * XZW + DINNER + ch) : 0.f;
    }

    for (int s = 0; s < LL; s++) {
        int slot = s & 1;
        float dtv = pdt[slot], xv = pxv[slot], Bv = pB[slot], Cv = pC[slot], zv = pz[slot];
        if (s + 2 < LL) {
            size_t rn = rowbase + t0 + (s + 2) * step;
            pdt[slot] = __ldg(dt + rn * DINNER + ch);
            pxv[slot] = __ldg(xc + rn * DINNER + ch);
            pB[slot]  = __ldg(bc + rn * 32 + n);
            pC[slot]  = __ldg(bc + rn * 32 + 16 + n);
            if (n == 0) pz[slot] = __ldg(xz + rn * XZW + DINNER + ch);
        }

        float a = __expf(dtv * Ac);
        h = fmaf(a, h, dtv * xv * Bv);
        float yp = h * Cv;
#pragma unroll
        for (int o = 8; o; o >>= 1)
            yp += __shfl_xor_sync(0xffffffffu, yp, o, 16);
        if (n == 0) {
            size_t r = rowbase + t0 + s * step;
            float sz = zv / (1.f + __expf(-zv));
            y[r * DINNER + ch] = (yp + xv * Dv) * sz;
        }
    }
}

// ---------------- host side ----------------
static void launch_gemm2(const float* A0, const float* A1, int lda, int acol0, int acol1,
                         const float* W0, const float* W1, int N, int K,
                         const float* b0, const float* b1,
                         float* o00, float* o01, int ldc, int ccol0, int ccol1,
                         float* o10, float* o11, int mode, int ndir)
{
    dim3 grid((N + BN - 1) / BN, NROWS / BM, ndir);
    tf32_gemm<<<grid, 256>>>(A0, A1, lda, acol0, acol1, W0, W1, N, K,
                             b0, b1, o00, o01, ldc, ccol0, ccol1, o10, o11, mode);
}

extern "C" void kernel_launch(void* const* d_in, const int* in_sizes, int n_in,
                              void* d_out, int out_size)
{
    const float* x         = (const float*)d_in[0];
    const float* in_norm_w = (const float*)d_in[1];
    const float* in_norm_b = (const float*)d_in[2];
    const float* ip_w      = (const float*)d_in[3];
    const float* ip_b      = (const float*)d_in[4];
    const float* dir_in_w [2] = {(const float*)d_in[5],  (const float*)d_in[16]};
    const float* dir_in_b [2] = {(const float*)d_in[6],  (const float*)d_in[17]};
    const float* dir_cw   [2] = {(const float*)d_in[7],  (const float*)d_in[18]};
    const float* dir_cb   [2] = {(const float*)d_in[8],  (const float*)d_in[19]};
    const float* dir_xp_w [2] = {(const float*)d_in[9],  (const float*)d_in[20]};
    const float* dir_dt_w [2] = {(const float*)d_in[10], (const float*)d_in[21]};
    const float* dir_dt_b [2] = {(const float*)d_in[11], (const float*)d_in[22]};
    const float* dir_Alog [2] = {(const float*)d_in[12], (const float*)d_in[23]};
    const float* dir_D    [2] = {(const float*)d_in[13], (const float*)d_in[24]};
    const float* dir_ow   [2] = {(const float*)d_in[14], (const float*)d_in[25]};
    const float* dir_ob   [2] = {(const float*)d_in[15], (const float*)d_in[26]};
    const float* op_w      = (const float*)d_in[27];
    const float* op_b      = (const float*)d_in[28];
    const float* norm_w    = (const float*)d_in[29];
    const float* norm_b    = (const float*)d_in[30];
    float* out = (float*)d_out;

    void* p;
    cudaGetSymbolAddress(&p, g_xn);  float* xn  = (float*)p;
    cudaGetSymbolAddress(&p, g_xp);  float* xp  = (float*)p;
    cudaGetSymbolAddress(&p, g_xz);  float* xzb = (float*)p;
    cudaGetSymbolAddress(&p, g_xc);  float* xcb = (float*)p;
    cudaGetSymbolAddress(&p, g_bc);  float* bcb = (float*)p;
    cudaGetSymbolAddress(&p, g_dt);  float* dtb = (float*)p;
    cudaGetSymbolAddress(&p, g_y);   float* yb  = (float*)p;
    cudaGetSymbolAddress(&p, g_cat); float* cat = (float*)p;
    cudaGetSymbolAddress(&p, g_tmp); float* tmp = (float*)p;
    cudaGetSymbolAddress(&p, g_wc);  float* wcb = (float*)p;

    float* xz[2] = {xzb, xzb + (size_t)NROWS * XZW};
    float* xc[2] = {xcb, xcb + (size_t)NROWS * DINNER};
    float* bc[2] = {bcb, bcb + (size_t)NROWS * 32};
    float* dt[2] = {dtb, dtb + (size_t)NROWS * DINNER};
    float* yy[2] = {yb,  yb  + (size_t)NROWS * DINNER};
    float* wc[2] = {wcb, wcb + (size_t)DINNER * WCN};

    // 0) combined dt/BC weights
    int wcg = (DINNER * WCN + 255) / 256;
    wc_kernel<<<wcg, 256>>>(dir_xp_w[0], dir_dt_w[0], wc[0]);
    wc_kernel<<<wcg, 256>>>(dir_xp_w[1], dir_dt_w[1], wc[1]);

    // 1) input layernorm
    ln_kernel<<<NROWS, 256>>>(x, nullptr, in_norm_w, in_norm_b, xn);

    // 2) input projection
    launch_gemm2(xn, xn, DM, 0, 0, ip_w, ip_w, DM, DM, ip_b, ip_b,
                 xp, xp, DM, 0, 0, nullptr, nullptr, 0, 1);

    // 3) per-dir in-proj (both dirs, one launch)
    launch_gemm2(xp, xp, DM, 0, DIN, dir_in_w[0], dir_in_w[1], XZW, DIN,
                 dir_in_b[0], dir_in_b[1], xz[0], xz[1], XZW, 0, 0,
                 nullptr, nullptr, 0, 2);

    // 4) depthwise conv + silu, both dirs
    conv_silu2<<<dim3((NROWS * DINNER) / 256, 2), 256>>>(
        xz[0], xz[1], dir_cw[0], dir_cb[0], dir_cw[1], dir_cb[1], xc[0], xc[1]);

    // 5) combined dt / B,C GEMM (both dirs, one launch)
    launch_gemm2(xc[0], xc[1], DINNER, 0, 0, wc[0], wc[1], WCN, DINNER,
                 dir_dt_b[0], dir_dt_b[1], dt[0], dt[1], 0, 0, 0,
                 bc[0], bc[1], 1, 2);

    // 6) selective scan, both dirs
    scan2<<<dim3(DINNER / 16, BB, 2), 256>>>(
        dt[0], dt[1], xc[0], xc[1], bc[0], bc[1], xz[0], xz[1],
        dir_Alog[0], dir_Alog[1], dir_D[0], dir_D[1], yy[0], yy[1]);

    // 7) out projections into concat buffer (both dirs, one launch)
    launch_gemm2(yy[0], yy[1], DINNER, 0, 0, dir_ow[0], dir_ow[1], DIN, DINNER,
                 dir_ob[0], dir_ob[1], cat, cat, DM, 0, DIN,
                 nullptr, nullptr, 0, 2);

    // 8) final projection
    launch_gemm2(cat, cat, DM, 0, 0, op_w, op_w, DM, DM, op_b, op_b,
                 tmp, tmp, DM, 0, 0, nullptr, nullptr, 0, 1);

    // 9) residual add + layernorm
    ln_kernel<<<NROWS, 256>>>(tmp, x, norm_w, norm_b, out);

    (void)in_sizes; (void)n_in; (void)out_size;
}

// round 4
// speedup vs baseline: 5.3063x; 1.4870x over previous
#include <cuda_runtime.h>
#include <cuda_bf16.h>
#include <cstdint>

// ---------------- problem constants ----------------
#define BB      2
#define LL      2048
#define DM      768
#define DIN     384
#define DINNER  768
#define DTR     24
#define DST     16
#define XZW     1536
#define NROWS   (BB*LL)
#define WCN     800
#define NC      16          // scan chunks
#define CL      (LL/NC)     // 128 steps per chunk
#define EPSV    1e-5f
#define LOG2E   1.4426950408889634f

typedef __nv_bfloat16 bf16;

// ---------------- scratch ----------------
__device__ bf16  g_xnb [NROWS*DM];          // ln1 out (bf16, GEMM input)
__device__ bf16  g_xpb [NROWS*DM];          // ip out (bf16)
__device__ float g_xz  [2][NROWS*XZW];      // in-proj out (fp32: conv + z gate)
__device__ float g_xc  [2][NROWS*DINNER];   // conv out fp32 (scan)
__device__ bf16  g_xcb [2][NROWS*DINNER];   // conv out bf16 (dtbc GEMM)
__device__ float g_bc  [2][NROWS*32];       // B|C fp32
__device__ float g_dt  [2][NROWS*DINNER];   // softplus dt fp32
__device__ bf16  g_yb  [2][NROWS*DINNER];   // scan out bf16 (out-proj input)
__device__ bf16  g_catb[NROWS*DM];          // concat bf16 (op input)
__device__ float g_tmp [NROWS*DM];          // op out fp32
// chunked-scan state
__device__ float g_P  [2*BB*NC*DINNER*DST];
__device__ float g_S  [2*BB*NC*DINNER*DST];
__device__ float g_Hin[2*BB*NC*DINNER*DST];
// transposed bf16 weights [N][K]
__device__ bf16 g_wip [DM*DM];
__device__ bf16 g_win [2][XZW*DIN];
__device__ bf16 g_wwc [2][WCN*DINNER];
__device__ bf16 g_wow [2][DIN*DINNER];
__device__ bf16 g_wop [DM*DM];

// ---------------- cp.async ----------------
__device__ __forceinline__ void cp16(uint32_t dst, const void* src, int srcsize) {
    asm volatile("cp.async.cg.shared.global [%0], [%1], 16, %2;\n"
                 :: "r"(dst), "l"(src), "r"(srcsize));
}
#define CP_COMMIT asm volatile("cp.async.commit_group;\n" ::: "memory")
#define CP_WAIT0  asm volatile("cp.async.wait_group 0;\n" ::: "memory")

// ---------------- weight convert+transpose: fp32 [K][N] -> bf16 [N][K] -------
struct CvtJobs {
    const float* src[6];
    bf16* dst[6];
    int K[6], N[6];
};
__global__ void cvtT_kernel(CvtJobs j)
{
    int id = blockIdx.z;
    const float* src = j.src[id];
    bf16* dst = j.dst[id];
    int K = j.K[id], N = j.N[id];
    int bx = blockIdx.x * 32, by = blockIdx.y * 32;
    if (bx >= N || by >= K) return;
    __shared__ float t[32][33];
    int tx = threadIdx.x, ty = threadIdx.y;
#pragma unroll
    for (int i = 0; i < 32; i += 8) {
        int k = by + ty + i, n = bx + tx;
        t[ty + i][tx] = (k < K && n < N) ? src[(size_t)k * N + n] : 0.f;
    }
    __syncthreads();
#pragma unroll
    for (int i = 0; i < 32; i += 8) {
        int n = bx + ty + i, k = by + tx;
        if (n < N && k < K)
            dst[(size_t)n * K + k] = __float2bfloat16(t[tx][ty + i]);
    }
}

// ---------------- combined dt/BC weight, transposed bf16 [800][768] ----------
__global__ void wcT_kernel(const float* __restrict__ xpw0, const float* __restrict__ dtw0,
                           const float* __restrict__ xpw1, const float* __restrict__ dtw1,
                           bf16* wc0, bf16* wc1)
{
    int d = blockIdx.z;
    const float* xp_w = d ? xpw1 : xpw0;
    const float* dt_w = d ? dtw1 : dtw0;
    bf16* wc = d ? wc1 : wc0;
    int n = blockIdx.y;
    int k = blockIdx.x * 256 + threadIdx.x;
    if (k >= DINNER) return;
    float v;
    if (n < DINNER) {
        v = 0.f;
#pragma unroll
        for (int r = 0; r < DTR; r++)
            v = fmaf(xp_w[k * 56 + r], dt_w[r * DINNER + n], v);
    } else {
        v = xp_w[k * 56 + DTR + (n - DINNER)];
    }
    wc[(size_t)n * DINNER + k] = __float2bfloat16(v);
}

// ---------------- layernorm: out fp32 or bf16, optional residual -------------
__global__ void ln_kernel(const float* __restrict__ a,
                          const float* __restrict__ add,
                          const float* __restrict__ w,
                          const float* __restrict__ b,
                          float* __restrict__ outf,
                          bf16* __restrict__ outh)
{
    int row = blockIdx.x;
    const float* pa = a + (size_t)row * DM;
    const float* pd = add ? add + (size_t)row * DM : nullptr;

    float v[3];
    float s = 0.f, sq = 0.f;
#pragma unroll
    for (int i = 0; i < 3; i++) {
        int idx = threadIdx.x + i * 256;
        float t = pa[idx];
        if (pd) t += pd[idx];
        v[i] = t;
        s += t; sq += t * t;
    }
#pragma unroll
    for (int o = 16; o; o >>= 1) {
        s  += __shfl_xor_sync(0xffffffffu, s,  o);
        sq += __shfl_xor_sync(0xffffffffu, sq, o);
    }
    __shared__ float ss[8], ssq[8];
    int wid = threadIdx.x >> 5, ln = threadIdx.x & 31;
    if (ln == 0) { ss[wid] = s; ssq[wid] = sq; }
    __syncthreads();
    if (threadIdx.x == 0) {
        float S = 0.f, Q = 0.f;
#pragma unroll
        for (int i = 0; i < 8; i++) { S += ss[i]; Q += ssq[i]; }
        ss[0] = S; ssq[0] = Q;
    }
    __syncthreads();
    float mean = ss[0] * (1.f / DM);
    float var  = ssq[0] * (1.f / DM) - mean * mean;
    float rs   = rsqrtf(var + EPSV);

#pragma unroll
    for (int i = 0; i < 3; i++) {
        int idx = threadIdx.x + i * 256;
        float r = (v[i] - mean) * rs * w[idx] + b[idx];
        if (outf) outf[(size_t)row * DM + idx] = r;
        else      outh[(size_t)row * DM + idx] = __float2bfloat16(r);
    }
}

// ---------------- bf16 tensor-core GEMM, cp.async double buffered ------------
// A bf16 [M][lda] (col offset acol), W bf16 [N][K] transposed.
// mode 0: fp32 out f[row*ldc+ccol+col] = v+bias
// mode 1: dtbc: col<768 -> f = softplus(v+bias); col>=768 -> x[row*32+col-768] = v
// mode 2: bf16 out h[row*ldc+ccol+col] = v+bias
#define BM 128
#define BN 64
#define BKK 32
#define AP 40   /* bf16 pitch (20 words) */
#define BP 40

__global__ __launch_bounds__(256, 3)
void bf16_gemm(const bf16* __restrict__ A0, const bf16* __restrict__ A1,
               int lda, int acol0, int acol1,
               const bf16* __restrict__ W0, const bf16* __restrict__ W1,
               int N, int K,
               const float* __restrict__ bias0, const float* __restrict__ bias1,
               float* f0, float* f1, bf16* h0, bf16* h1,
               int ldc, int ccol0, int ccol1,
               float* x0, float* x1, int mode)
{
    int z = blockIdx.z;
    const bf16* A = z ? A1 : A0;
    const bf16* W = z ? W1 : W0;
    const float* bias = z ? bias1 : bias0;
    float* fo = z ? f1 : f0;
    bf16*  ho = z ? h1 : h0;
    float* xo = z ? x1 : x0;
    int acol = z ? acol1 : acol0;
    int ccol = z ? ccol1 : ccol0;

    __shared__ bf16 As[2][BM * AP];
    __shared__ bf16 Bs[2][BN * BP];

    int bm = blockIdx.y * BM;
    int bn = blockIdx.x * BN;
    int tid = threadIdx.x, lane = tid & 31, warp = tid >> 5;
    int wm = warp >> 1, wn = warp & 1;
    int gid = lane >> 2, tid4 = lane & 3;

    // cp.async coords
    int ar0 = (tid * 2) >> 2,     ac0 = ((tid * 2) & 3) * 8;
    int ar1 = (tid * 2 + 1) >> 2, ac1 = ((tid * 2 + 1) & 3) * 8;
    int br = tid >> 2, bcq = (tid & 3) * 8;
    int bvalid = (bn + br) < N;
    const bf16* bsrc = W + (bvalid ? ((size_t)(bn + br) * K + bcq) : 0);
    int bsz = bvalid ? 16 : 0;
    const bf16* asrc0 = A + (size_t)(bm + ar0) * lda + acol + ac0;
    const bf16* asrc1 = A + (size_t)(bm + ar1) * lda + acol + ac1;

    float acc[2][4][4];
#pragma unroll
    for (int a = 0; a < 2; a++)
#pragma unroll
        for (int b = 0; b < 4; b++)
#pragma unroll
            for (int c = 0; c < 4; c++) acc[a][b][c] = 0.f;

    // prologue
    cp16((uint32_t)__cvta_generic_to_shared(&As[0][ar0 * AP + ac0]), asrc0, 16);
    cp16((uint32_t)__cvta_generic_to_shared(&As[0][ar1 * AP + ac1]), asrc1, 16);
    cp16((uint32_t)__cvta_generic_to_shared(&Bs[0][br * BP + bcq]), bsrc, bsz);
    CP_COMMIT;

    int niter = K / BKK;
    int cur = 0;
    for (int i = 0; i < niter; i++) {
        CP_WAIT0;
        __syncthreads();
        if (i + 1 < niter) {
            int k0 = (i + 1) * BKK;
            cp16((uint32_t)__cvta_generic_to_shared(&As[cur ^ 1][ar0 * AP + ac0]), asrc0 + k0, 16);
            cp16((uint32_t)__cvta_generic_to_shared(&As[cur ^ 1][ar1 * AP + ac1]), asrc1 + k0, 16);
            cp16((uint32_t)__cvta_generic_to_shared(&Bs[cur ^ 1][br * BP + bcq]), bsrc + k0, bsz);
            CP_COMMIT;
        }

        const uint32_t* As32 = reinterpret_cast<const uint32_t*>(&As[cur][0]);
        const uint32_t* Bs32 = reinterpret_cast<const uint32_t*>(&Bs[cur][0]);
#pragma unroll
        for (int cc = 0; cc < 2; cc++) {
            int kb2 = cc * 8;  // word offset of k16-chunk
            uint32_t af[2][4], bf[4][2];
#pragma unroll
            for (int mt = 0; mt < 2; mt++) {
                int m0 = wm * 32 + mt * 16 + gid;
                af[mt][0] = As32[m0 * 20 + kb2 + tid4];
                af[mt][1] = As32[(m0 + 8) * 20 + kb2 + tid4];
                af[mt][2] = As32[m0 * 20 + kb2 + tid4 + 4];
                af[mt][3] = As32[(m0 + 8) * 20 + kb2 + tid4 + 4];
            }
#pragma unroll
            for (int nt = 0; nt < 4; nt++) {
                int n0 = wn * 32 + nt * 8 + gid;
                bf[nt][0] = Bs32[n0 * 20 + kb2 + tid4];
                bf[nt][1] = Bs32[n0 * 20 + kb2 + tid4 + 4];
            }
#pragma unroll
            for (int mt = 0; mt < 2; mt++)
#pragma unroll
                for (int nt = 0; nt < 4; nt++) {
                    asm volatile(
                        "mma.sync.aligned.m16n8k16.row.col.f32.bf16.bf16.f32 "
                        "{%0,%1,%2,%3}, {%4,%5,%6,%7}, {%8,%9}, {%0,%1,%2,%3};\n"
                        : "+f"(acc[mt][nt][0]), "+f"(acc[mt][nt][1]),
                          "+f"(acc[mt][nt][2]), "+f"(acc[mt][nt][3])
                        : "r"(af[mt][0]), "r"(af[mt][1]), "r"(af[mt][2]), "r"(af[mt][3]),
                          "r"(bf[nt][0]), "r"(bf[nt][1]));
                }
        }
        __syncthreads();
        cur ^= 1;
    }

    // epilogue
#pragma unroll
    for (int mt = 0; mt < 2; mt++) {
#pragma unroll
        for (int nt = 0; nt < 4; nt++) {
#pragma unroll
            for (int c = 0; c < 4; c++) {
                int row = bm + wm * 32 + mt * 16 + gid + ((c >= 2) ? 8 : 0);
                int col = bn + wn * 32 + nt * 8 + tid4 * 2 + (c & 1);
                if (col >= N) continue;
                float v = acc[mt][nt][c];
                if (mode == 0) {
                    if (bias) v += bias[col];
                    fo[(size_t)row * ldc + ccol + col] = v;
                } else if (mode == 1) {
                    if (col < DINNER) {
                        v += bias[col];
                        v = (v > 20.f) ? v : log1pf(__expf(v));
                        fo[(size_t)row * DINNER + col] = v;
                    } else {
                        xo[(size_t)row * 32 + (col - DINNER)] = v;
                    }
                } else {
                    if (bias) v += bias[col];
                    ho[(size_t)row * ldc + ccol + col] = __float2bfloat16(v);
                }
            }
        }
    }
}

// ---------------- depthwise conv + SiLU (fp32 + bf16 outputs) ----------------
__global__ void conv_silu2(const float* __restrict__ xz0, const float* __restrict__ xz1,
                           const float* __restrict__ cw0, const float* __restrict__ cb0,
                           const float* __restrict__ cw1, const float* __restrict__ cb1,
                           float* of0, float* of1, bf16* oh0, bf16* oh1)
{
    int dir = blockIdx.y;
    const float* xz = dir ? xz1 : xz0;
    const float* cw = dir ? cw1 : cw0;
    const float* cb = dir ? cb1 : cb0;
    float* of = dir ? of1 : of0;
    bf16*  oh = dir ? oh1 : oh0;

    int idx = blockIdx.x * blockDim.x + threadIdx.x;
    if (idx >= NROWS * DINNER) return;
    int d = idx % DINNER;
    int row = idx / DINNER;
    int b = row / LL, l = row % LL;

    float acc = cb[d];
    if (dir == 0) {
#pragma unroll
        for (int k = 0; k < 4; k++) {
            int ls = l - 3 + k;
            if (ls >= 0)
                acc = fmaf(cw[d * 4 + k], xz[((size_t)b * LL + ls) * XZW + d], acc);
        }
    } else {
#pragma unroll
        for (int k = 0; k < 4; k++) {
            int ls = l + 3 - k;
            if (ls < LL)
                acc = fmaf(cw[d * 4 + k], xz[((size_t)b * LL + ls) * XZW + d], acc);
        }
    }
    float r = acc / (1.f + __expf(-acc));
    of[idx] = r;
    oh[idx] = __float2bfloat16(r);
}

// ---------------- chunked scan ----------------
// z = dir*BB + b ; chunk = blockIdx.y ; 16 channels per block (8 warps x 2)
__global__ void scan_pass1(const float* __restrict__ dt0, const float* __restrict__ dt1,
                           const float* __restrict__ xc0, const float* __restrict__ xc1,
                           const float* __restrict__ bc0, const float* __restrict__ bc1,
                           const float* __restrict__ A0,  const float* __restrict__ A1,
                           float* __restrict__ P, float* __restrict__ S)
{
    int zz = blockIdx.z;
    int dir = zz >> 1, b = zz & 1;
    const float* dt = dir ? dt1 : dt0;
    const float* xc = dir ? xc1 : xc0;
    const float* bc = dir ? bc1 : bc0;
    const float* Al = dir ? A1 : A0;

    int lane = threadIdx.x & 31;
    int warp = threadIdx.x >> 5;
    int n = lane & 15;
    int ch = blockIdx.x * 16 + warp * 2 + (lane >> 4);
    int c = blockIdx.y;

    float Ac2 = -__expf(Al[ch * DST + n]) * LOG2E;
    float h = 0.f, p = 1.f;
    size_t rowbase = (size_t)b * LL;
    int s0 = c * CL;
    for (int j = 0; j < CL; j++) {
        int s = s0 + j;
        int t = dir ? (LL - 1 - s) : s;
        size_t r = rowbase + t;
        float dtv = __ldg(dt + r * DINNER + ch);
        float xv  = __ldg(xc + r * DINNER + ch);
        float Bv  = __ldg(bc + r * 32 + n);
        float a = exp2f(dtv * Ac2);
        h = fmaf(a, h, dtv * xv * Bv);
        p *= a;
    }
    size_t idx = ((size_t)(zz * NC + c) * DINNER + ch) * DST + n;
    P[idx] = p;
    S[idx] = h;
}

__global__ void scan_mid(const float* __restrict__ P, const float* __restrict__ S,
                         float* __restrict__ Hin)
{
    int gid = blockIdx.x * 256 + threadIdx.x;   // over 4*12288
    int zz = gid / (DINNER * DST);
    int r  = gid % (DINNER * DST);
    float h = 0.f;
#pragma unroll
    for (int c = 0; c < NC; c++) {
        size_t idx = (size_t)(zz * NC + c) * (DINNER * DST) + r;
        Hin[idx] = h;
        h = fmaf(P[idx], h, S[idx]);
    }
}

__global__ void scan_pass2(const float* __restrict__ dt0, const float* __restrict__ dt1,
                           const float* __restrict__ xc0, const float* __restrict__ xc1,
                           const float* __restrict__ bc0, const float* __restrict__ bc1,
                           const float* __restrict__ xz0, const float* __restrict__ xz1,
                           const float* __restrict__ A0,  const float* __restrict__ A1,
                           const float* __restrict__ D0,  const float* __restrict__ D1,
                           const float* __restrict__ Hin,
                           bf16* __restrict__ y0, bf16* __restrict__ y1)
{
    int zz = blockIdx.z;
    int dir = zz >> 1, b = zz & 1;
    const float* dt = dir ? dt1 : dt0;
    const float* xc = dir ? xc1 : xc0;
    const float* bc = dir ? bc1 : bc0;
    const float* xz = dir ? xz1 : xz0;
    const float* Al = dir ? A1 : A0;
    const float* Dp = dir ? D1 : D0;
    bf16* y = dir ? y1 : y0;

    int lane = threadIdx.x & 31;
    int warp = threadIdx.x >> 5;
    int n = lane & 15;
    int ch = blockIdx.x * 16 + warp * 2 + (lane >> 4);
    int c = blockIdx.y;

    float Ac2 = -__expf(Al[ch * DST + n]) * LOG2E;
    float Dv = Dp[ch];
    float h = Hin[((size_t)(zz * NC + c) * DINNER + ch) * DST + n];
    size_t rowbase = (size_t)b * LL;
    int s0 = c * CL;
    for (int j = 0; j < CL; j++) {
        int s = s0 + j;
        int t = dir ? (LL - 1 - s) : s;
        size_t r = rowbase + t;
        float dtv = __ldg(dt + r * DINNER + ch);
        float xv  = __ldg(xc + r * DINNER + ch);
        float Bv  = __ldg(bc + r * 32 + n);
        float Cv  = __ldg(bc + r * 32 + 16 + n);
        float a = exp2f(dtv * Ac2);
        h = fmaf(a, h, dtv * xv * Bv);
        float yp = h * Cv;
#pragma unroll
        for (int o = 8; o; o >>= 1)
            yp += __shfl_xor_sync(0xffffffffu, yp, o, 16);
        if (n == 0) {
            float zv = __ldg(xz + r * XZW + DINNER + ch);
            float sz = zv / (1.f + __expf(-zv));
            y[r * DINNER + ch] = __float2bfloat16((yp + xv * Dv) * sz);
        }
    }
}

// ---------------- host side ----------------
static void launch_gemm(const bf16* A0, const bf16* A1, int lda, int acol0, int acol1,
                        const bf16* W0, const bf16* W1, int N, int K,
                        const float* b0, const float* b1,
                        float* f0, float* f1, bf16* h0, bf16* h1,
                        int ldc, int ccol0, int ccol1,
                        float* x0, float* x1, int mode, int ndir)
{
    dim3 grid((N + BN - 1) / BN, NROWS / BM, ndir);
    bf16_gemm<<<grid, 256>>>(A0, A1, lda, acol0, acol1, W0, W1, N, K,
                             b0, b1, f0, f1, h0, h1, ldc, ccol0, ccol1, x0, x1, mode);
}

template <typename T> static T* sym(const void* s) {
    void* p; cudaGetSymbolAddress(&p, s); return (T*)p;
}

extern "C" void kernel_launch(void* const* d_in, const int* in_sizes, int n_in,
                              void* d_out, int out_size)
{
    const float* x         = (const float*)d_in[0];
    const float* in_norm_w = (const float*)d_in[1];
    const float* in_norm_b = (const float*)d_in[2];
    const float* ip_w      = (const float*)d_in[3];
    const float* ip_b      = (const float*)d_in[4];
    const float* dir_in_w [2] = {(const float*)d_in[5],  (const float*)d_in[16]};
    const float* dir_in_b [2] = {(const float*)d_in[6],  (const float*)d_in[17]};
    const float* dir_cw   [2] = {(const float*)d_in[7],  (const float*)d_in[18]};
    const float* dir_cb   [2] = {(const float*)d_in[8],  (const float*)d_in[19]};
    const float* dir_xp_w [2] = {(const float*)d_in[9],  (const float*)d_in[20]};
    const float* dir_dt_w [2] = {(const float*)d_in[10], (const float*)d_in[21]};
    const float* dir_dt_b [2] = {(const float*)d_in[11], (const float*)d_in[22]};
    const float* dir_Alog [2] = {(const float*)d_in[12], (const float*)d_in[23]};
    const float* dir_D    [2] = {(const float*)d_in[13], (const float*)d_in[24]};
    const float* dir_ow   [2] = {(const float*)d_in[14], (const float*)d_in[25]};
    const float* dir_ob   [2] = {(const float*)d_in[15], (const float*)d_in[26]};
    const float* op_w      = (const float*)d_in[27];
    const float* op_b      = (const float*)d_in[28];
    const float* norm_w    = (const float*)d_in[29];
    const float* norm_b    = (const float*)d_in[30];
    float* out = (float*)d_out;

    void* p;
    cudaGetSymbolAddress(&p, g_xnb);  bf16*  xnb  = (bf16*)p;
    cudaGetSymbolAddress(&p, g_xpb);  bf16*  xpb  = (bf16*)p;
    cudaGetSymbolAddress(&p, g_xz);   float* xzb  = (float*)p;
    cudaGetSymbolAddress(&p, g_xc);   float* xcb  = (float*)p;
    cudaGetSymbolAddress(&p, g_xcb);  bf16*  xchb = (bf16*)p;
    cudaGetSymbolAddress(&p, g_bc);   float* bcb  = (float*)p;
    cudaGetSymbolAddress(&p, g_dt);   float* dtb  = (float*)p;
    cudaGetSymbolAddress(&p, g_yb);   bf16*  ybb  = (bf16*)p;
    cudaGetSymbolAddress(&p, g_catb); bf16*  catb = (bf16*)p;
    cudaGetSymbolAddress(&p, g_tmp);  float* tmp  = (float*)p;
    cudaGetSymbolAddress(&p, g_P);    float* Pb   = (float*)p;
    cudaGetSymbolAddress(&p, g_S);    float* Sb   = (float*)p;
    cudaGetSymbolAddress(&p, g_Hin);  float* Hinb = (float*)p;
    cudaGetSymbolAddress(&p, g_wip);  bf16*  wip  = (bf16*)p;
    cudaGetSymbolAddress(&p, g_win);  bf16*  winb = (bf16*)p;
    cudaGetSymbolAddress(&p, g_wwc);  bf16*  wwcb = (bf16*)p;
    cudaGetSymbolAddress(&p, g_wow);  bf16*  wowb = (bf16*)p;
    cudaGetSymbolAddress(&p, g_wop);  bf16*  wop  = (bf16*)p;

    float* xz[2] = {xzb, xzb + (size_t)NROWS * XZW};
    float* xc[2] = {xcb, xcb + (size_t)NROWS * DINNER};
    bf16*  xch[2] = {xchb, xchb + (size_t)NROWS * DINNER};
    float* bc[2] = {bcb, bcb + (size_t)NROWS * 32};
    float* dt[2] = {dtb, dtb + (size_t)NROWS * DINNER};
    bf16*  yy[2] = {ybb, ybb + (size_t)NROWS * DINNER};
    bf16*  win[2] = {winb, winb + (size_t)XZW * DIN};
    bf16*  wwc[2] = {wwcb, wwcb + (size_t)WCN * DINNER};
    bf16*  wow[2] = {wowb, wowb + (size_t)DIN * DINNER};

    // 0) weight prep: convert+transpose to bf16 [N][K]
    CvtJobs jobs;
    jobs.src[0] = ip_w;        jobs.dst[0] = wip;    jobs.K[0] = DM;     jobs.N[0] = DM;
    jobs.src[1] = dir_in_w[0]; jobs.dst[1] = win[0]; jobs.K[1] = DIN;    jobs.N[1] = XZW;
    jobs.src[2] = dir_in_w[1]; jobs.dst[2] = win[1]; jobs.K[2] = DIN;    jobs.N[2] = XZW;
    jobs.src[3] = dir_ow[0];   jobs.dst[3] = wow[0]; jobs.K[3] = DINNER; jobs.N[3] = DIN;
    jobs.src[4] = dir_ow[1];   jobs.dst[4] = wow[1]; jobs.K[4] = DINNER; jobs.N[4] = DIN;
    jobs.src[5] = op_w;        jobs.dst[5] = wop;    jobs.K[5] = DM;     jobs.N[5] = DM;
    cvtT_kernel<<<dim3(48, 24, 6), dim3(32, 8)>>>(jobs);
    wcT_kernel<<<dim3(3, WCN, 2), 256>>>(dir_xp_w[0], dir_dt_w[0],
                                         dir_xp_w[1], dir_dt_w[1], wwc[0], wwc[1]);

    // 1) ln1 -> bf16
    ln_kernel<<<NROWS, 256>>>(x, nullptr, in_norm_w, in_norm_b, nullptr, xnb);

    // 2) ip GEMM -> xp bf16
    launch_gemm(xnb, xnb, DM, 0, 0, wip, wip, DM, DM, ip_b, ip_b,
                nullptr, nullptr, xpb, xpb, DM, 0, 0, nullptr, nullptr, 2, 1);

    // 3) in-proj (both dirs) -> xz fp32
    launch_gemm(xpb, xpb, DM, 0, DIN, win[0], win[1], XZW, DIN,
                dir_in_b[0], dir_in_b[1], xz[0], xz[1], nullptr, nullptr,
                XZW, 0, 0, nullptr, nullptr, 0, 2);

    // 4) conv + silu -> xc fp32 + bf16
    conv_silu2<<<dim3((NROWS * DINNER) / 256, 2), 256>>>(
        xz[0], xz[1], dir_cw[0], dir_cb[0], dir_cw[1], dir_cb[1],
        xc[0], xc[1], xch[0], xch[1]);

    // 5) dtbc GEMM (both dirs) -> dt fp32 (softplus), bc fp32
    launch_gemm(xch[0], xch[1], DINNER, 0, 0, wwc[0], wwc[1], WCN, DINNER,
                dir_dt_b[0], dir_dt_b[1], dt[0], dt[1], nullptr, nullptr,
                0, 0, 0, bc[0], bc[1], 1, 2);

    // 6) chunked scan
    scan_pass1<<<dim3(DINNER / 16, NC, 2 * BB), 256>>>(
        dt[0], dt[1], xc[0], xc[1], bc[0], bc[1],
        dir_Alog[0], dir_Alog[1], Pb, Sb);
    scan_mid<<<(2 * BB * DINNER * DST) / 256, 256>>>(Pb, Sb, Hinb);
    scan_pass2<<<dim3(DINNER / 16, NC, 2 * BB), 256>>>(
        dt[0], dt[1], xc[0], xc[1], bc[0], bc[1], xz[0], xz[1],
        dir_Alog[0], dir_Alog[1], dir_D[0], dir_D[1], Hinb, yy[0], yy[1]);

    // 7) out-proj (both dirs) -> cat bf16
    launch_gemm(yy[0], yy[1], DINNER, 0, 0, wow[0], wow[1], DIN, DINNER,
                dir_ob[0], dir_ob[1], nullptr, nullptr, catb, catb,
                DM, 0, DIN, nullptr, nullptr, 2, 2);

    // 8) op GEMM -> tmp fp32
    launch_gemm(catb, catb, DM, 0, 0, wop, wop, DM, DM, op_b, op_b,
                tmp, tmp, nullptr, nullptr, DM, 0, 0, nullptr, nullptr, 0, 1);

    // 9) residual + ln -> out fp32
    ln_kernel<<<NROWS, 256>>>(tmp, x, norm_w, norm_b, out, nullptr);

    (void)in_sizes; (void)n_in; (void)out_size;
}